// round 1
// baseline (speedup 1.0000x reference)
#include <cuda_runtime.h>

#define BB 8
#define LL 4096
#define DD 1024
#define MAXW 720
#define CHUNK 256
#define RING 1024
#define RPAD 1025
#define OPAD 257

// ---------------------------------------------------------------------------
// Moving-average half: odd 32-channel groups. y[t] = x[t] + m1 * sum_{tau<w} x[t-tau]
// where m1 = ma_r_kernel[i,1] = -1/w. Sliding-window running sum per channel.
// ---------------------------------------------------------------------------
__global__ __launch_bounds__(256, 1) void ma_kernel(const float* __restrict__ u,
                                                    const float* __restrict__ ma_k,
                                                    float* __restrict__ out) {
    extern __shared__ float sm[];
    float* ring  = sm;                 // 32 * 1025 floats (odd stride -> conflict-free)
    float* otile = sm + 32 * RPAD;     // 32 * 257 floats

    const int tid  = threadIdx.x;
    const int warp = tid >> 5;
    const int lane = tid & 31;
    const int g    = 2 * blockIdx.x + 1;      // odd 32-channel group
    const int d0   = g * 32;
    const int b    = blockIdx.y;
    const size_t base = (size_t)b * LL * DD + d0;

    // zero the ring so x[t-w] for t<w reads 0.0f (slot analysis: those slots are
    // never overwritten before they are consumed)
    for (int i = tid; i < 32 * RPAD; i += 256) ring[i] = 0.0f;

    // per-channel window parameters (used by the scan warp; computed everywhere)
    const int d    = d0 + lane;
    const int i_ma = ((d >> 6) << 2) + ((d >> 3) & 7) - 4;   // 0..63
    const float m1 = ma_k[i_ma * MAXW + 1];                  // = -1/w
    const int   w  = (int)rintf(-1.0f / m1);
    float win = 0.0f;

    __syncthreads();

    for (int t0 = 0; t0 < LL; t0 += CHUNK) {
        // ---- cooperative coalesced load of 256 timesteps x 32 channels ----
        #pragma unroll 4
        for (int r = warp; r < CHUNK; r += 8) {
            const int t = t0 + r;
            ring[lane * RPAD + (t & (RING - 1))] = u[base + (size_t)t * DD + lane];
        }
        __syncthreads();

        // ---- warp 0: per-channel serial sliding-window scan ----
        if (warp == 0) {
            const int pn = t0 & (RING - 1);          // no wrap within a chunk
            int po = (t0 - w) & (RING - 1);
            #pragma unroll 8
            for (int tt = 0; tt < CHUNK; tt++) {
                const float xn = ring[lane * RPAD + pn + tt];
                const float xo = ring[lane * RPAD + po];
                po = (po + 1) & (RING - 1);
                win += xn - xo;
                otile[lane * OPAD + tt] = fmaf(m1, win, xn);
            }
        }
        __syncthreads();

        // ---- cooperative coalesced store ----
        #pragma unroll 4
        for (int r = warp; r < CHUNK; r += 8) {
            out[base + (size_t)(t0 + r) * DD + lane] = otile[lane * OPAD + r];
        }
        __syncthreads();
    }
}

// ---------------------------------------------------------------------------
// Differencing half: even 32-channel groups. 4-tap causal stencil, coefficients
// pascal[nk][k] read from the diff_kernel input (rows 0..3 == pascal).
// ---------------------------------------------------------------------------
__global__ __launch_bounds__(256) void diff_stencil_kernel(const float* __restrict__ u,
                                                           const float* __restrict__ dk,
                                                           float* __restrict__ out) {
    const int g  = blockIdx.x;                        // 0..15 -> even group pairs
    const int d  = g * 64 + threadIdx.x;              // 32 channels, (d>>5) even
    const int b  = blockIdx.z;
    const int t0 = (blockIdx.y * 8 + threadIdx.y) * 8;

    const int nk = (d >> 3) & 3;
    const float c0 = dk[nk * 4 + 0];
    const float c1 = dk[nk * 4 + 1];
    const float c2 = dk[nk * 4 + 2];
    const float c3 = dk[nk * 4 + 3];

    const size_t base = (size_t)b * LL * DD + d;

    float x1 = (t0 >= 1) ? u[base + (size_t)(t0 - 1) * DD] : 0.0f;
    float x2 = (t0 >= 2) ? u[base + (size_t)(t0 - 2) * DD] : 0.0f;
    float x3 = (t0 >= 3) ? u[base + (size_t)(t0 - 3) * DD] : 0.0f;

    #pragma unroll
    for (int tt = 0; tt < 8; tt++) {
        const int t = t0 + tt;
        const float x0 = u[base + (size_t)t * DD];
        out[base + (size_t)t * DD] = c0 * x0 + c1 * x1 + c2 * x2 + c3 * x3;
        x3 = x2; x2 = x1; x1 = x0;
    }
}

extern "C" void kernel_launch(void* const* d_in, const int* in_sizes, int n_in,
                              void* d_out, int out_size) {
    const float* u  = (const float*)d_in[0];   // (B, L, D)
    const float* dk = (const float*)d_in[1];   // (64, 4)
    const float* mk = (const float*)d_in[2];   // (64, 720)
    float* out = (float*)d_out;                // (B, L, D)

    const size_t smem = (size_t)(32 * RPAD + 32 * OPAD) * sizeof(float);
    cudaFuncSetAttribute(ma_kernel, cudaFuncAttributeMaxDynamicSharedMemorySize, (int)smem);

    ma_kernel<<<dim3(16, BB), 256, smem>>>(u, mk, out);
    diff_stencil_kernel<<<dim3(16, 64, BB), dim3(32, 8)>>>(u, dk, out);
}

// round 2
// speedup vs baseline: 2.5768x; 2.5768x over previous
#include <cuda_runtime.h>

#define BB 8
#define LL 4096
#define DD 1024
#define MAXW 720
#define CHUNK 256
#define CH 16            // channels per MA block
#define RING 1024
#define RPAD 1025        // ring row stride (floats)
#define TPAD 257         // x/y tile row stride (floats)

// ---------------------------------------------------------------------------
// Moving-average half via prefix sums.
//   y[t] = x[t] + m1 * (S[t] - S[t-w]),  S = inclusive prefix sum,  m1 = -1/w
// Block: 16 channels (half of an odd 32-group) x full L, chunked by 256 steps.
// Phase A: coalesced load -> smem tile (transposed)
// Phase B: each warp owns 2 channels; Kogge-Stone warp scans build S into a
//          1024-deep ring; y computed in-place in the tile.
// Phase C: coalesced store.
// ---------------------------------------------------------------------------
__global__ __launch_bounds__(256, 2) void ma_kernel(const float* __restrict__ u,
                                                    const float* __restrict__ ma_k,
                                                    float* __restrict__ out) {
    extern __shared__ float sm[];
    float* ring = sm;               // CH * RPAD floats
    float* tile = sm + CH * RPAD;   // CH * TPAD floats

    const int tid  = threadIdx.x;
    const int warp = tid >> 5;
    const int lane = tid & 31;
    const int h    = blockIdx.x;                 // 0..31 : half-group index
    const int g    = 2 * (h >> 1) + 1;           // odd 32-channel group
    const int d0   = g * 32 + (h & 1) * 16;      // first of 16 channels
    const int b    = blockIdx.y;
    const size_t base = (size_t)b * LL * DD + d0;

    // zero ring: slots for negative times must read 0.0f
    for (int i = tid; i < CH * RPAD; i += 256) ring[i] = 0.0f;

    // per-warp channel parameters (2 channels per warp)
    float m1v[2]; int wv[2]; float carry[2];
    #pragma unroll
    for (int cc = 0; cc < 2; cc++) {
        const int ch = warp * 2 + cc;
        const int d  = d0 + ch;
        const int i_ma = ((d >> 6) << 2) + ((d >> 3) & 7) - 4;   // 0..63
        m1v[cc]  = ma_k[i_ma * MAXW + 1];                        // = -1/w
        wv[cc]   = (int)rintf(-1.0f / m1v[cc]);
        carry[cc] = 0.0f;
    }

    const int c_ld = tid & 15;        // channel for load/store phases
    const int r_ld = tid >> 4;        // starting row

    __syncthreads();

    for (int t0 = 0; t0 < LL; t0 += CHUNK) {
        // ---- Phase A: coalesced load (B,L,D) -> tile[ch][r] ----
        #pragma unroll
        for (int k = 0; k < 16; k++) {
            const int r = r_ld + k * 16;
            tile[c_ld * TPAD + r] = u[base + (size_t)(t0 + r) * DD + c_ld];
        }
        __syncthreads();

        // ---- Phase B: per-warp prefix scans + y in place ----
        #pragma unroll
        for (int cc = 0; cc < 2; cc++) {
            const int ch = warp * 2 + cc;
            const float m1 = m1v[cc];
            const int  w   = wv[cc];
            float cr = carry[cc];
            #pragma unroll
            for (int s = 0; s < CHUNK / 32; s++) {
                const int t = t0 + s * 32 + lane;
                const float x = tile[ch * TPAD + s * 32 + lane];
                float v = x;
                #pragma unroll
                for (int off = 1; off < 32; off <<= 1) {
                    const float n = __shfl_up_sync(0xffffffffu, v, off);
                    if (lane >= off) v += n;
                }
                const float S = v + cr;
                ring[ch * RPAD + (t & (RING - 1))] = S;
                __syncwarp();
                const float So = ring[ch * RPAD + ((t - w) & (RING - 1))];
                tile[ch * TPAD + s * 32 + lane] = fmaf(m1, S - So, x);
                cr += __shfl_sync(0xffffffffu, v, 31);
            }
            carry[cc] = cr;
        }
        __syncthreads();

        // ---- Phase C: coalesced store ----
        #pragma unroll
        for (int k = 0; k < 16; k++) {
            const int r = r_ld + k * 16;
            out[base + (size_t)(t0 + r) * DD + c_ld] = tile[c_ld * TPAD + r];
        }
        __syncthreads();
    }
}

// ---------------------------------------------------------------------------
// Differencing half: even 32-channel groups, 4-tap causal stencil.
// 16 timesteps per thread (tap reload overhead 19/16).
// ---------------------------------------------------------------------------
__global__ __launch_bounds__(256) void diff_stencil_kernel(const float* __restrict__ u,
                                                           const float* __restrict__ dk,
                                                           float* __restrict__ out) {
    const int g  = blockIdx.x;                        // 0..15
    const int d  = g * 64 + threadIdx.x;              // 32 channels, even 32-group
    const int b  = blockIdx.z;
    const int t0 = (blockIdx.y * 8 + threadIdx.y) * 16;

    const int nk = (d >> 3) & 3;
    const float c0 = dk[nk * 4 + 0];
    const float c1 = dk[nk * 4 + 1];
    const float c2 = dk[nk * 4 + 2];
    const float c3 = dk[nk * 4 + 3];

    const size_t base = (size_t)b * LL * DD + d;

    float x1 = (t0 >= 1) ? u[base + (size_t)(t0 - 1) * DD] : 0.0f;
    float x2 = (t0 >= 2) ? u[base + (size_t)(t0 - 2) * DD] : 0.0f;
    float x3 = (t0 >= 3) ? u[base + (size_t)(t0 - 3) * DD] : 0.0f;

    #pragma unroll
    for (int tt = 0; tt < 16; tt++) {
        const int t = t0 + tt;
        const float x0 = u[base + (size_t)t * DD];
        out[base + (size_t)t * DD] = c0 * x0 + c1 * x1 + c2 * x2 + c3 * x3;
        x3 = x2; x2 = x1; x1 = x0;
    }
}

extern "C" void kernel_launch(void* const* d_in, const int* in_sizes, int n_in,
                              void* d_out, int out_size) {
    const float* u  = (const float*)d_in[0];   // (B, L, D)
    const float* dk = (const float*)d_in[1];   // (64, 4)
    const float* mk = (const float*)d_in[2];   // (64, 720)
    float* out = (float*)d_out;                // (B, L, D)

    const size_t smem = (size_t)(CH * RPAD + CH * TPAD) * sizeof(float);
    cudaFuncSetAttribute(ma_kernel, cudaFuncAttributeMaxDynamicSharedMemorySize, (int)smem);

    ma_kernel<<<dim3(32, BB), 256, smem>>>(u, mk, out);
    diff_stencil_kernel<<<dim3(16, 32, BB), dim3(32, 8)>>>(u, dk, out);
}

// round 3
// speedup vs baseline: 2.7598x; 1.0710x over previous
#include <cuda_runtime.h>

#define BB 8
#define LL 4096
#define DD 1024
#define MAXW 720
#define CHUNK 256
#define CH 16            // channels per MA block
#define RING 1024
#define RPAD 1028        // ring row stride (floats, 16B-aligned rows)
#define TPAD 260         // tile row stride (floats, 16B-aligned rows)

// ---------------------------------------------------------------------------
// Moving-average half via prefix sums, warp-specialized.
//   y[t] = x[t] + m1*(S[t] - S[t-w]),  S = inclusive prefix sum,  m1 = -1/w
// Warps 0-3: scan 4 channels each (3-step scan, one shfl-chain per 256 elems).
// Warps 4-7: producer — float4 gmem load of next chunk + store of previous
//            chunk's y, double-buffered tiles, y computed in place.
// One __syncthreads per chunk.
// ---------------------------------------------------------------------------
__global__ __launch_bounds__(256, 2) void ma_kernel(const float* __restrict__ u,
                                                    const float* __restrict__ ma_k,
                                                    float* __restrict__ out) {
    extern __shared__ float sm[];
    float* ring = sm;                        // CH * RPAD
    float* xt0  = sm + CH * RPAD;            // CH * TPAD
    float* xt1  = xt0 + CH * TPAD;           // CH * TPAD

    const int tid  = threadIdx.x;
    const int warp = tid >> 5;
    const int lane = tid & 31;
    const int h    = blockIdx.x;                 // 0..31
    const int g    = 2 * (h >> 1) + 1;           // odd 32-channel group
    const int d0   = g * 32 + (h & 1) * 16;      // first of 16 channels
    const int b    = blockIdx.y;

    const float4* u4 = (const float4*)u;
    float4*       o4 = (float4*)out;
    // float4 index of (b, t, d0): rows of D/4 = 256 float4s
    const size_t base4 = (size_t)b * LL * (DD / 4) + (d0 >> 2);

    // zero ring: negative-time slots must read 0.0f
    for (int i = tid; i < CH * RPAD; i += 256) ring[i] = 0.0f;

    // consumer per-channel params (warps 0-3, 4 channels each)
    float m1v[4]; int wv[4]; float carry[4];
    if (warp < 4) {
        #pragma unroll
        for (int cc = 0; cc < 4; cc++) {
            const int d = d0 + warp * 4 + cc;
            const int i_ma = ((d >> 6) << 2) + ((d >> 3) & 7) - 4;
            m1v[cc]  = ma_k[i_ma * MAXW + 1];          // = -1/w
            wv[cc]   = (int)rintf(-1.0f / m1v[cc]);
            carry[cc] = 0.0f;
        }
    }

    // producer mapping (warps 4-7): 128 threads cover 4 float4-cols x 32 rows
    const int ptid = tid - 128;
    const int c4   = ptid & 3;          // float4 column (16 ch = 4 float4)
    const int tr   = ptid >> 2;         // row 0..31

    // prologue: producers load chunk 0 into xt0
    if (warp >= 4) {
        #pragma unroll
        for (int k = 0; k < 8; k++) {
            const int r = tr + 32 * k;
            const float4 f = u4[base4 + (size_t)r * (DD / 4) + c4];
            float* col = xt0 + (c4 * 4) * TPAD + r;
            col[0 * TPAD] = f.x; col[1 * TPAD] = f.y;
            col[2 * TPAD] = f.z; col[3 * TPAD] = f.w;
        }
    }
    __syncthreads();

    for (int ci = 0; ci <= 16; ci++) {
        const int p = ci & 1;
        float* cur = p ? xt1 : xt0;
        float* alt = p ? xt0 : xt1;

        if (warp < 4) {
            if (ci < 16) {
                const int t0 = ci * CHUNK;
                const int rb = t0 & (RING - 1);            // ring base (0/256/512/768)
                #pragma unroll
                for (int cc = 0; cc < 4; cc++) {
                    const int ch = warp * 4 + cc;
                    float* trow = cur + ch * TPAD;
                    float* rrow = ring + ch * RPAD;
                    const float4 a = *(const float4*)(trow + lane * 8);
                    const float4 bq = *(const float4*)(trow + lane * 8 + 4);
                    // serial inclusive prefix of 8
                    float p0 = a.x, p1 = p0 + a.y, p2 = p1 + a.z, p3 = p2 + a.w;
                    float p4 = p3 + bq.x, p5 = p4 + bq.y, p6 = p5 + bq.z, p7 = p6 + bq.w;
                    // warp inclusive scan over per-thread totals
                    float v = p7;
                    #pragma unroll
                    for (int off = 1; off < 32; off <<= 1) {
                        const float n = __shfl_up_sync(0xffffffffu, v, off);
                        if (lane >= off) v += n;
                    }
                    const float bs = (v - p7) + carry[cc];   // exclusive + carry
                    float4 s0, s1;
                    s0.x = p0 + bs; s0.y = p1 + bs; s0.z = p2 + bs; s0.w = p3 + bs;
                    s1.x = p4 + bs; s1.y = p5 + bs; s1.z = p6 + bs; s1.w = p7 + bs;
                    *(float4*)(rrow + rb + lane * 8)     = s0;
                    *(float4*)(rrow + rb + lane * 8 + 4) = s1;
                    carry[cc] += __shfl_sync(0xffffffffu, v, 31);
                    __syncwarp();
                    const float m1 = m1v[cc];
                    const int  w   = wv[cc];
                    #pragma unroll
                    for (int s = 0; s < 8; s++) {
                        const int tt = s * 32 + lane;
                        const float Sv = rrow[rb + tt];
                        const float So = rrow[(t0 + tt - w) & (RING - 1)];
                        const float x  = trow[tt];
                        trow[tt] = fmaf(m1, Sv - So, x);
                    }
                    __syncwarp();
                }
            }
        } else {
            // store y of chunk ci-1, then load chunk ci+1 (same buffer 'alt')
            if (ci >= 1) {
                const int t0s = (ci - 1) * CHUNK;
                const float* col = alt + (c4 * 4) * TPAD;
                #pragma unroll
                for (int k = 0; k < 8; k++) {
                    const int r = tr + 32 * k;
                    float4 f;
                    f.x = col[0 * TPAD + r]; f.y = col[1 * TPAD + r];
                    f.z = col[2 * TPAD + r]; f.w = col[3 * TPAD + r];
                    o4[base4 + (size_t)(t0s + r) * (DD / 4) + c4] = f;
                }
            }
            if (ci < 15) {
                const int t0l = (ci + 1) * CHUNK;
                float* col = alt + (c4 * 4) * TPAD;
                #pragma unroll
                for (int k = 0; k < 8; k++) {
                    const int r = tr + 32 * k;
                    const float4 f = u4[base4 + (size_t)(t0l + r) * (DD / 4) + c4];
                    col[0 * TPAD + r] = f.x; col[1 * TPAD + r] = f.y;
                    col[2 * TPAD + r] = f.z; col[3 * TPAD + r] = f.w;
                }
            }
        }
        __syncthreads();
    }
}

// ---------------------------------------------------------------------------
// Differencing half: even 32-channel groups, 4-tap causal stencil, float4.
// Thread owns 4 channels (same taps) x 16 consecutive timesteps.
// ---------------------------------------------------------------------------
__global__ __launch_bounds__(256) void diff_stencil_kernel(const float* __restrict__ u,
                                                           const float* __restrict__ dk,
                                                           float* __restrict__ out) {
    const int g    = blockIdx.x;                 // 0..15 (even 32-groups)
    const int b    = blockIdx.z;
    const int warp = threadIdx.x >> 5;
    const int lane = threadIdx.x & 31;
    const int c4   = lane & 7;                   // 8 float4 = 32 channels
    const int ts   = warp * 4 + (lane >> 3);     // time slot 0..31
    const int d    = g * 64 + c4 * 4;
    const int t0   = blockIdx.y * 512 + ts * 16;

    const int nk = (d >> 3) & 3;
    const float c0 = dk[nk * 4 + 0];
    const float c1 = dk[nk * 4 + 1];
    const float c2 = dk[nk * 4 + 2];
    const float c3 = dk[nk * 4 + 3];

    const float4* u4 = (const float4*)u;
    float4*       o4 = (float4*)out;
    const size_t base4 = (size_t)b * LL * (DD / 4) + (d >> 2);

    float4 x1 = {0.f,0.f,0.f,0.f}, x2 = x1, x3 = x1;
    if (t0 > 0) {
        x1 = u4[base4 + (size_t)(t0 - 1) * (DD / 4)];
        x2 = u4[base4 + (size_t)(t0 - 2) * (DD / 4)];
        x3 = u4[base4 + (size_t)(t0 - 3) * (DD / 4)];
    }

    #pragma unroll
    for (int tt = 0; tt < 16; tt++) {
        const float4 x0 = u4[base4 + (size_t)(t0 + tt) * (DD / 4)];
        float4 o;
        o.x = fmaf(c0, x0.x, fmaf(c1, x1.x, fmaf(c2, x2.x, c3 * x3.x)));
        o.y = fmaf(c0, x0.y, fmaf(c1, x1.y, fmaf(c2, x2.y, c3 * x3.y)));
        o.z = fmaf(c0, x0.z, fmaf(c1, x1.z, fmaf(c2, x2.z, c3 * x3.z)));
        o.w = fmaf(c0, x0.w, fmaf(c1, x1.w, fmaf(c2, x2.w, c3 * x3.w)));
        o4[base4 + (size_t)(t0 + tt) * (DD / 4)] = o;
        x3 = x2; x2 = x1; x1 = x0;
    }
}

extern "C" void kernel_launch(void* const* d_in, const int* in_sizes, int n_in,
                              void* d_out, int out_size) {
    const float* u  = (const float*)d_in[0];   // (B, L, D)
    const float* dk = (const float*)d_in[1];   // (64, 4)
    const float* mk = (const float*)d_in[2];   // (64, 720)
    float* out = (float*)d_out;                // (B, L, D)

    const size_t smem = (size_t)(CH * RPAD + 2 * CH * TPAD) * sizeof(float);
    cudaFuncSetAttribute(ma_kernel, cudaFuncAttributeMaxDynamicSharedMemorySize, (int)smem);

    ma_kernel<<<dim3(32, BB), 256, smem>>>(u, mk, out);
    diff_stencil_kernel<<<dim3(16, 8, BB), 256>>>(u, dk, out);
}